// round 10
// baseline (speedup 1.0000x reference)
#include <cuda_runtime.h>
#include <cstdint>

#define NS 2
#define NB 8
#define NC 32
#define NH 128
#define NW 128
#define NM 32
#define RH 64
#define RW 64

#define PSTRIDE 132   // 128 data cols + 4 pad (conflict softening + safe overread)
#define SMEM_BYTES (NH * PSTRIDE * 4)   // 67584

// One block = one (n,b,c) plane (64 KB, contiguous in fm).
// Phase 1: stage plane into (dynamic) SMEM, zero the 4-col pad.
// Phase 2: loop over the 32 ROIs of this (n,b): gather from SMEM (LDS),
//          store dense 64x64 tiles with STG.128.CS.

__global__ __launch_bounds__(512) void roi_patch_kernel(
    const float* __restrict__ fm,
    const int*   __restrict__ boxes,
    float*       __restrict__ out)
{
    extern __shared__ __align__(16) float plane[];

    const int blk = blockIdx.x;           // (n*8 + b)*32 + c
    const int c   = blk & 31;
    const int nb  = blk >> 5;             // n*8 + b  (0..15)

    // ---- Phase 1: load plane (16384 floats = 4096 float4) ----
    const float4* pg = reinterpret_cast<const float4*>(fm) + ((size_t)blk << 12);
    #pragma unroll
    for (int i = 0; i < 8; ++i) {
        const int lin = threadIdx.x + (i << 9);   // 0..4095
        const int row = lin >> 5;
        const int c4  = lin & 31;
        const float4 v = __ldg(pg + lin);
        *reinterpret_cast<float4*>(&plane[row * PSTRIDE + (c4 << 2)]) = v;
    }
    if (threadIdx.x < NH) {   // zero pad cols 128..131 of each row
        *reinterpret_cast<float4*>(&plane[threadIdx.x * PSTRIDE + NW]) =
            make_float4(0.f, 0.f, 0.f, 0.f);
    }
    __syncthreads();

    // ---- Phase 2: 32 ROIs ----
    const int r   = threadIdx.x >> 3;       // 0..63
    const int c0  = (threadIdx.x & 7) << 3; // 0,8,...,56
    const int4* boxp = reinterpret_cast<const int4*>(boxes) + nb * NM;
    float* dst0 = out + (((size_t)(nb * NM) * NC + c) << 12) + (r << 6) + c0;

    #pragma unroll 1
    for (int m = 0; m < NM; ++m) {
        const int4 box = __ldg(boxp + m);
        const int x1   = box.x;
        const int y1   = box.y;
        const int wbox = box.z - x1;
        const int hbox = box.w - y1;
        const int off  = x1 & 3;

        float4 o0 = make_float4(0.f, 0.f, 0.f, 0.f);
        float4 o1 = make_float4(0.f, 0.f, 0.f, 0.f);

        if (r < hbox && c0 < wbox) {
            const float* base = &plane[(y1 + r) * PSTRIDE + (x1 - off) + c0];
            const float4 A = *reinterpret_cast<const float4*>(base);
            const float4 B = *reinterpret_cast<const float4*>(base + 4);
            if (off == 0) {
                o0 = A; o1 = B;
            } else {
                const float4 C = *reinterpret_cast<const float4*>(base + 8);
                if (off == 1) {
                    o0 = make_float4(A.y, A.z, A.w, B.x);
                    o1 = make_float4(B.y, B.z, B.w, C.x);
                } else if (off == 2) {
                    o0 = make_float4(A.z, A.w, B.x, B.y);
                    o1 = make_float4(B.z, B.w, C.x, C.y);
                } else {
                    o0 = make_float4(A.w, B.x, B.y, B.z);
                    o1 = make_float4(B.w, C.x, C.y, C.z);
                }
            }
            if (c0 + 1 >= wbox) o0.y = 0.f;
            if (c0 + 2 >= wbox) o0.z = 0.f;
            if (c0 + 3 >= wbox) o0.w = 0.f;
            if (c0 + 4 >= wbox) o1.x = 0.f;
            if (c0 + 5 >= wbox) o1.y = 0.f;
            if (c0 + 6 >= wbox) o1.z = 0.f;
            if (c0 + 7 >= wbox) o1.w = 0.f;
        }

        float* dst = dst0 + ((size_t)m << 17);   // m*32*4096
        __stcs(reinterpret_cast<float4*>(dst), o0);
        __stcs(reinterpret_cast<float4*>(dst + 4), o1);
    }
}

extern "C" void kernel_launch(void* const* d_in, const int* in_sizes, int n_in,
                              void* d_out, int out_size)
{
    const float* fm    = (const float*)d_in[0];
    const int*   boxes = (const int*)d_in[1];
    float*       out   = (float*)d_out;

    // Idempotent; no allocation; safe on every call (incl. graph capture).
    cudaFuncSetAttribute(roi_patch_kernel,
                         cudaFuncAttributeMaxDynamicSharedMemorySize,
                         SMEM_BYTES);

    const int blocks = NS * NB * NC;   // 512 planes
    roi_patch_kernel<<<blocks, 512, SMEM_BYTES>>>(fm, boxes, out);
}

// round 11
// speedup vs baseline: 1.8701x; 1.8701x over previous
#include <cuda_runtime.h>
#include <cstdint>

#define NS 2
#define NB 8
#define NC 32
#define NH 128
#define NW 128
#define NM 32
#define RH 64
#define RW 64

// One block = one (n, bm, c) output tile of 64x64 floats (16 KB).
// 256 threads; each thread writes 4 float4s at rows r0, r0+16, r0+32, r0+48.
// x1 alignment (off = x1 & 3) is block-uniform -> compile-time-shift bodies.
// Best measured variant (48.06 us): aligned A/B float4 loads + register
// compose, STG.128.CS streaming stores. Nine structural experiments show the
// kernel is pinned at the chip's write-bandwidth operating point (~5 TB/s
// effective HBM writes); this is the floor configuration.

template <int OFF>
__device__ __forceinline__ void tile_body(
    const float* __restrict__ srcA,   // aligned: plane + (y1+r0)*NW + (x1-OFF) + c0
    float* __restrict__ dst,          // out tile + r0*64 + c0
    int r0, int c0, int hbox, int wbox)
{
    const bool cv  = c0 < wbox;        // any column of this float4 valid
    const bool m1  = (c0 + 1) < wbox;
    const bool m2  = (c0 + 2) < wbox;
    const bool m3  = (c0 + 3) < wbox;

    #pragma unroll
    for (int i = 0; i < 4; ++i) {
        const int r = r0 + (i << 4);
        float4 val = make_float4(0.f, 0.f, 0.f, 0.f);
        if (r < hbox && cv) {
            const float4* p = reinterpret_cast<const float4*>(srcA + (i << 4) * NW);
            const float4 A = __ldg(p);
            if (OFF == 0) {
                val = A;
            } else {
                const float4 B = __ldg(p + 1);
                if (OFF == 1) val = make_float4(A.y, A.z, A.w, B.x);
                if (OFF == 2) val = make_float4(A.z, A.w, B.x, B.y);
                if (OFF == 3) val = make_float4(A.w, B.x, B.y, B.z);
            }
            if (!m1) val.y = 0.f;
            if (!m2) val.z = 0.f;
            if (!m3) val.w = 0.f;
        }
        __stcs(reinterpret_cast<float4*>(dst + ((i << 4) << 6)), val);
    }
}

__global__ __launch_bounds__(256) void roi_patch_kernel(
    const float* __restrict__ fm,
    const int*   __restrict__ boxes,
    float*       __restrict__ out)
{
    const int blk = blockIdx.x;
    const int c   = blk & 31;
    const int bm  = (blk >> 5) & 255;
    const int n   = blk >> 13;
    const int b   = bm >> 5;
    const int m   = bm & 31;

    __shared__ int4 sbox;
    if (threadIdx.x == 0) {
        sbox = reinterpret_cast<const int4*>(boxes)[(n * NB + b) * NM + m];
    }
    __syncthreads();

    const int x1   = sbox.x;
    const int y1   = sbox.y;
    const int wbox = sbox.z - x1;   // valid cols: cc < wbox  (8..64)
    const int hbox = sbox.w - y1;   // valid rows: r  < hbox  (8..64)
    const int off  = x1 & 3;        // block-uniform

    const int lane16 = threadIdx.x & 15;
    const int r0     = threadIdx.x >> 4;     // 0..15
    const int c0     = lane16 << 2;

    const float* srcA = fm
        + (((size_t)(n * NB + b) * NC + c) * NH + (y1 + r0)) * NW
        + (x1 - off) + c0;                   // 16B-aligned
    float* dst = out + ((size_t)blk << 12) + (r0 << 6) + c0;

    switch (off) {
        case 0: tile_body<0>(srcA, dst, r0, c0, hbox, wbox); break;
        case 1: tile_body<1>(srcA, dst, r0, c0, hbox, wbox); break;
        case 2: tile_body<2>(srcA, dst, r0, c0, hbox, wbox); break;
        default: tile_body<3>(srcA, dst, r0, c0, hbox, wbox); break;
    }
}

extern "C" void kernel_launch(void* const* d_in, const int* in_sizes, int n_in,
                              void* d_out, int out_size)
{
    const float* fm    = (const float*)d_in[0];
    const int*   boxes = (const int*)d_in[1];
    float*       out   = (float*)d_out;

    const int blocks = NS * NB * NM * NC;   // 16384 tiles
    roi_patch_kernel<<<blocks, 256>>>(fm, boxes, out);
}